// round 11
// baseline (speedup 1.0000x reference)
#include <cuda_runtime.h>
#include <math.h>

// Problem constants
#define NN 10000      // nodes
#define NE 160000     // edges
#define FIN 4         // input features
#define HID 32        // hidden
#define NC 4          // classes
#define EB 8          // edges per smem batch in kB4
#define CHUNK 32      // edges per warp in kB4 (NE/CHUNK = 5000 warps, exact)
#define NWARP (NE / CHUNK)

typedef unsigned long long ull;

// ---- packed fp32x2 helpers (sm_103a) ----
#define FMA2(d, a, b, c) \
    asm("fma.rn.f32x2 %0, %1, %2, %3;" : "=l"(d) : "l"(a), "l"(b), "l"(c))
#define PACK2(d, lo, hi) \
    asm("mov.b64 %0, {%1, %2};" : "=l"(d) : "r"(__float_as_uint(lo)), "r"(__float_as_uint(hi)))
#define UNPACK2(lo, hi, v) do { unsigned _ul, _uh;                        \
    asm("mov.b64 {%0, %1}, %2;" : "=r"(_ul), "=r"(_uh) : "l"(v));          \
    lo = __uint_as_float(_ul); hi = __uint_as_float(_uh); } while (0)

// ---------------- device scratch (static globals: allowed) ----------------
__device__ float g_G[NN * HID * HID];    // [n, j, o]  40.96 MB (L2-resident)
__device__ float g_B[NN * HID];          // per-src b2 term
__device__ float g_agg[2][NN * HID];     // ping-pong accumulators
// edge sort-by-src structures
__device__ int    g_deg[NN];
__device__ int    g_start[NN + 1];
__device__ int    g_cur[NN];
__device__ int    g_sdst[NE];
__device__ float2 g_sea[NE];
__device__ int    g_cnode[NWARP];        // first node of each 32-edge chunk

// ---------------------------------------------------------------------------
// Edge counting sort (once per launch; edges shared by all 3 layers)
// ---------------------------------------------------------------------------
__global__ __launch_bounds__(256) void k_zero() {
    int t = blockIdx.x * 256 + threadIdx.x;
    if (t < NN) g_deg[t] = 0;
}

__global__ __launch_bounds__(256) void k_hist(const int* __restrict__ ei) {
    int e = blockIdx.x * 256 + threadIdx.x;
    if (e < NE) atomicAdd(&g_deg[ei[e]], 1);   // return unused -> REDG
}

__global__ __launch_bounds__(256) void k_scan() {
    __shared__ int part[256];
    const int PER = (NN + 255) / 256;   // 40
    int tid = threadIdx.x;
    int base = tid * PER;
    int s = 0;
    for (int k = 0; k < PER; k++) {
        int i = base + k;
        if (i < NN) s += g_deg[i];
    }
    part[tid] = s;
    __syncthreads();
    for (int off = 1; off < 256; off <<= 1) {
        int v = (tid >= off) ? part[tid - off] : 0;
        __syncthreads();
        part[tid] += v;
        __syncthreads();
    }
    int run = tid ? part[tid - 1] : 0;
    for (int k = 0; k < PER; k++) {
        int i = base + k;
        if (i < NN) {
            g_start[i] = run;
            g_cur[i] = run;
            run += g_deg[i];
        }
    }
    if (tid == 255) g_start[NN] = part[255];
}

__global__ __launch_bounds__(256) void k_scatter(const int* __restrict__ ei,
                                                 const float* __restrict__ ea) {
    int e = blockIdx.x * 256 + threadIdx.x;
    if (e >= NE) return;
    int src = ei[e];
    int pos = atomicAdd(&g_cur[src], 1);
    g_sdst[pos] = ei[NE + e];
    g_sea[pos] = make_float2(ea[2 * e], ea[2 * e + 1]);
}

// g_cnode[W] = node whose edge range contains edge W*CHUNK (binary search)
__global__ __launch_bounds__(256) void k_cnode() {
    int W = blockIdx.x * 256 + threadIdx.x;
    if (W >= NWARP) return;
    int target = W * CHUNK;
    int lo = 0, hi = NN - 1;
    while (lo < hi) {
        int mid = (lo + hi + 1) >> 1;
        if (g_start[mid] <= target) lo = mid; else hi = mid - 1;
    }
    g_cnode[W] = lo;
}

// ---------------------------------------------------------------------------
// kAF: fused G-GEMM + B + agg-init.  16 nodes per 256-thread block.
//   G[n, j*32+o] = sum_i x[n,i] * w2[j*(DIN*32) + i*32 + o]
//   B[n,o]      = sum_i x[n,i] * b2[i*32+o]
//   agg[wr][n,o]= bias[o] + sum_i x[n,i]*root[i*32+o]
// ---------------------------------------------------------------------------
template<int DIN, int MODE>
__global__ __launch_bounds__(256) void kAF(const float* __restrict__ xext,
                                           const float* __restrict__ w2,
                                           const float* __restrict__ b2,
                                           const float* __restrict__ root,
                                           const float* __restrict__ bias,
                                           int rd, int wr) {
    __shared__ float xsf[16][DIN];
    __shared__ ull   xs2[8][DIN];
    const int base = blockIdx.x * 16;
    const int tid = threadIdx.x;

    for (int idx = tid; idx < 16 * DIN; idx += 256) {
        int m = idx / DIN, i = idx % DIN;
        int n = base + m;
        xsf[m][i] = MODE ? fmaxf(g_agg[rd][n * DIN + i], 0.f)
                         : xext[n * DIN + i];
    }
    __syncthreads();
    for (int idx = tid; idx < 8 * DIN; idx += 256) {
        int p = idx / DIN, i = idx % DIN;
        ull t;
        PACK2(t, xsf[2 * p][i], xsf[2 * p + 1][i]);
        xs2[p][i] = t;
    }
    __syncthreads();

    ull acc2[8][4];
#pragma unroll
    for (int p = 0; p < 8; p++)
#pragma unroll
        for (int k = 0; k < 4; k++) PACK2(acc2[p][k], 0.f, 0.f);

#pragma unroll 4
    for (int i = 0; i < DIN; i++) {
        ull wp[4];
#pragma unroll
        for (int k = 0; k < 4; k++) {
            int col = tid + 256 * k;                  // col = j*32 + o
            float wv = w2[(col >> 5) * (DIN * 32) + i * 32 + (col & 31)];
            PACK2(wp[k], wv, wv);
        }
#pragma unroll
        for (int p = 0; p < 8; p++) {
            ull x2 = xs2[p][i];
#pragma unroll
            for (int k = 0; k < 4; k++) FMA2(acc2[p][k], x2, wp[k], acc2[p][k]);
        }
    }

#pragma unroll
    for (int p = 0; p < 8; p++) {
        int n0 = base + 2 * p;
#pragma unroll
        for (int k = 0; k < 4; k++) {
            float v0, v1;
            UNPACK2(v0, v1, acc2[p][k]);
            g_G[(size_t)n0 * 1024 + tid + 256 * k]       = v0;
            g_G[(size_t)(n0 + 1) * 1024 + tid + 256 * k] = v1;
        }
    }

    // --- B + agg-init: 512 (m,o) pairs over 256 threads ---
#pragma unroll
    for (int t = tid; t < 512; t += 256) {
        int m = t >> 5, o = t & 31;
        float b = 0.f;
        float a = bias[o];
#pragma unroll 4
        for (int i = 0; i < DIN; i++) {
            float xv = xsf[m][i];
            b = fmaf(xv, b2[i * 32 + o], b);
            a = fmaf(xv, root[i * 32 + o], a);
        }
        int n = base + m;
        g_B[n * 32 + o] = b;
        g_agg[wr][n * 32 + o] = a;
    }
}

// ---------------------------------------------------------------------------
// kB4: one warp per CHUNK of 32 src-sorted edges (perfect load balance).
//  - walk src segments within the chunk; reload the 16x f32x2 G tile only at
//    src boundaries (~3 per chunk)
//  - h + dst staged through smem per batch; contraction = 2 edges
//    interleaved, 4 independent FFMA2 chains
//  - 128B-coalesced REDG scatter to agg[wr][dst]
// ---------------------------------------------------------------------------
__global__ __launch_bounds__(128) void kB4(const float* __restrict__ w1,
                                           const float* __restrict__ b1, int wr) {
    __shared__ __align__(16) float hs[4][EB][32];
    __shared__ int ds[4][EB];
    const int w = threadIdx.x >> 5;
    const int lane = threadIdx.x & 31;
    const int W = blockIdx.x * 4 + w;
    int e = W * CHUNK;
    const int e_hi = e + CHUNK;                  // NE % CHUNK == 0
    int node = g_cnode[W];

    const float w10 = w1[lane], w11 = w1[32 + lane], b1v = b1[lane];
    float* __restrict__ aggp = g_agg[wr];
    ull zero2;
    PACK2(zero2, 0.f, 0.f);

    while (e < e_hi) {
        while (g_start[node + 1] <= e) node++;   // skip empty nodes
        const int seg_end = min(e_hi, g_start[node + 1]);

        const float* __restrict__ Gs = g_G + (size_t)node * 1024;
        ull G2[16];
#pragma unroll
        for (int q = 0; q < 16; q++) {
            float g0 = Gs[(2 * q) * 32 + lane];
            float g1 = Gs[(2 * q + 1) * 32 + lane];
            PACK2(G2[q], g0, g1);
        }
        float Bv = g_B[node * 32 + lane];
        ull accInit;
        PACK2(accInit, Bv, 0.f);

        for (int e0 = e; e0 < seg_end; e0 += EB) {
            const int cnt = min(EB, seg_end - e0);
#pragma unroll
            for (int k = 0; k < EB; k++) {
                if (k < cnt) {
                    float2 a = g_sea[e0 + k];
                    hs[w][k][lane] =
                        fmaxf(fmaf(a.x, w10, fmaf(a.y, w11, b1v)), 0.f);
                }
            }
            if (lane < cnt) ds[w][lane] = g_sdst[e0 + lane];
            __syncwarp();
            int k = 0;
            for (; k + 2 <= cnt; k += 2) {
                int d0 = ds[w][k];
                int d1 = ds[w][k + 1];
                const ulonglong2* __restrict__ hp0 =
                    reinterpret_cast<const ulonglong2*>(hs[w][k]);
                const ulonglong2* __restrict__ hp1 =
                    reinterpret_cast<const ulonglong2*>(hs[w][k + 1]);
                ull a0 = accInit, a1 = zero2;
                ull c0 = accInit, c1 = zero2;
#pragma unroll
                for (int q = 0; q < 8; q++) {
                    ulonglong2 h0 = hp0[q];
                    ulonglong2 h1 = hp1[q];
                    FMA2(a0, h0.x, G2[2 * q], a0);
                    FMA2(a1, h0.y, G2[2 * q + 1], a1);
                    FMA2(c0, h1.x, G2[2 * q], c0);
                    FMA2(c1, h1.y, G2[2 * q + 1], c1);
                }
                float l0, h0f, l1, h1f;
                UNPACK2(l0, h0f, a0);
                UNPACK2(l1, h1f, a1);
                atomicAdd(&aggp[d0 * 32 + lane], (l0 + h0f) + (l1 + h1f));
                UNPACK2(l0, h0f, c0);
                UNPACK2(l1, h1f, c1);
                atomicAdd(&aggp[d1 * 32 + lane], (l0 + h0f) + (l1 + h1f));
            }
            if (k < cnt) {
                int d0 = ds[w][k];
                const ulonglong2* __restrict__ hp0 =
                    reinterpret_cast<const ulonglong2*>(hs[w][k]);
                ull a0 = accInit, a1 = zero2;
#pragma unroll
                for (int q = 0; q < 8; q++) {
                    ulonglong2 h0 = hp0[q];
                    FMA2(a0, h0.x, G2[2 * q], a0);
                    FMA2(a1, h0.y, G2[2 * q + 1], a1);
                }
                float l0, h0f, l1, h1f;
                UNPACK2(l0, h0f, a0);
                UNPACK2(l1, h1f, a1);
                atomicAdd(&aggp[d0 * 32 + lane], (l0 + h0f) + (l1 + h1f));
            }
            __syncwarp();
        }
        e = seg_end;
    }
}

// ---------------------------------------------------------------------------
// kF: relu -> logits = x @ fc_w + fc_b -> log_softmax
// ---------------------------------------------------------------------------
__global__ __launch_bounds__(256) void kF(const float* __restrict__ fcw,
                                          const float* __restrict__ fcb,
                                          float* __restrict__ out, int rd) {
    int n = blockIdx.x * 256 + threadIdx.x;
    if (n >= NN) return;
    float l[NC];
#pragma unroll
    for (int c = 0; c < NC; c++) l[c] = fcb[c];
    const float4* xr = reinterpret_cast<const float4*>(g_agg[rd]) + n * 8;
#pragma unroll
    for (int q = 0; q < 8; q++) {
        float4 v = xr[q];
        float xv[4] = {fmaxf(v.x, 0.f), fmaxf(v.y, 0.f),
                       fmaxf(v.z, 0.f), fmaxf(v.w, 0.f)};
#pragma unroll
        for (int s = 0; s < 4; s++) {
            int o = q * 4 + s;
#pragma unroll
            for (int c = 0; c < NC; c++) l[c] = fmaf(xv[s], fcw[o * NC + c], l[c]);
        }
    }
    float m = l[0];
#pragma unroll
    for (int c = 1; c < NC; c++) m = fmaxf(m, l[c]);
    float s = 0.f;
#pragma unroll
    for (int c = 0; c < NC; c++) s += expf(l[c] - m);
    float lse = m + logf(s);
#pragma unroll
    for (int c = 0; c < NC; c++) out[n * NC + c] = l[c] - lse;
}

// ---------------------------------------------------------------------------
extern "C" void kernel_launch(void* const* d_in, const int* in_sizes, int n_in,
                              void* d_out, int out_size) {
    const float* x   = (const float*)d_in[0];   // [N, 4]
    const int*   ei  = (const int*)d_in[1];     // [2, E]
    const float* ea  = (const float*)d_in[2];   // [E, 2]
    const float *W1[3], *B1[3], *W2[3], *B2[3], *RT[3], *BI[3];
    for (int l = 0; l < 3; l++) {
        W1[l] = (const float*)d_in[3 + 6 * l + 0];
        B1[l] = (const float*)d_in[3 + 6 * l + 1];
        W2[l] = (const float*)d_in[3 + 6 * l + 2];
        B2[l] = (const float*)d_in[3 + 6 * l + 3];
        RT[l] = (const float*)d_in[3 + 6 * l + 4];
        BI[l] = (const float*)d_in[3 + 6 * l + 5];
    }
    const float* fcw = (const float*)d_in[21];
    const float* fcb = (const float*)d_in[22];
    float* out = (float*)d_out;

    const int gA = NN / 16;                     // 625 (exact)
    const int gB = (NWARP + 3) / 4;             // 1250 blocks x 4 warps
    const int gE = (NE + 255) / 256;            // 625
    const int gF = (NN + 255) / 256;
    const int gZ = (NN + 255) / 256;
    const int gC = (NWARP + 255) / 256;         // 20

    // ---- sort edges by src (once; shared by all layers) ----
    k_zero<<<gZ, 256>>>();
    k_hist<<<gE, 256>>>(ei);
    k_scan<<<1, 256>>>();
    k_scatter<<<gE, 256>>>(ei, ea);
    k_cnode<<<gC, 256>>>();

    // ---- layer 0 (din=4, external input, write agg[0]) ----
    kAF<FIN, 0><<<gA, 256>>>(x, W2[0], B2[0], RT[0], BI[0], 0, 0);
    kB4<<<gB, 128>>>(W1[0], B1[0], 0);

    // ---- layer 1 (din=32, read agg[0] w/ relu, write agg[1]) ----
    kAF<HID, 1><<<gA, 256>>>(nullptr, W2[1], B2[1], RT[1], BI[1], 0, 1);
    kB4<<<gB, 128>>>(W1[1], B1[1], 1);

    // ---- layer 2 (din=32, read agg[1] w/ relu, write agg[0]) ----
    kAF<HID, 1><<<gA, 256>>>(nullptr, W2[2], B2[2], RT[2], BI[2], 1, 0);
    kB4<<<gB, 128>>>(W1[2], B1[2], 0);

    // ---- classifier + log_softmax (relu on read) ----
    kF<<<gF, 256>>>(fcw, fcb, out, 0);
}

// round 13
// speedup vs baseline: 1.0290x; 1.0290x over previous
#include <cuda_runtime.h>
#include <math.h>

// Problem constants
#define NN 10000      // nodes
#define NE 160000     // edges
#define FIN 4         // input features
#define HID 32        // hidden
#define NC 4          // classes
#define EB 8          // edges per smem batch in kB3
#define NBK 64        // degree buckets for node scheduling order

typedef unsigned long long ull;

// ---- packed fp32x2 helpers (sm_103a) ----
#define FMA2(d, a, b, c) \
    asm("fma.rn.f32x2 %0, %1, %2, %3;" : "=l"(d) : "l"(a), "l"(b), "l"(c))
#define PACK2(d, lo, hi) \
    asm("mov.b64 %0, {%1, %2};" : "=l"(d) : "r"(__float_as_uint(lo)), "r"(__float_as_uint(hi)))
#define UNPACK2(lo, hi, v) do { unsigned _ul, _uh;                        \
    asm("mov.b64 {%0, %1}, %2;" : "=r"(_ul), "=r"(_uh) : "l"(v));          \
    lo = __uint_as_float(_ul); hi = __uint_as_float(_uh); } while (0)

// ---------------- device scratch (static globals: allowed) ----------------
__device__ float g_G[NN * HID * HID];    // [n, j, o]  40.96 MB (L2-resident)
__device__ float g_B[NN * HID];          // per-src b2 term
__device__ float g_agg[2][NN * HID];     // ping-pong accumulators
// edge sort-by-src structures
__device__ int    g_deg[NN];
__device__ int    g_start[NN + 1];
__device__ int    g_cur[NN];
__device__ int    g_sdst[NE];
__device__ float2 g_sea[NE];
// node scheduling order (descending degree buckets)
__device__ int    g_bhist[NBK];
__device__ int    g_bcur[NBK];
__device__ int    g_order[NN];

// ---------------------------------------------------------------------------
// Edge counting sort + degree-ordered node schedule (once per launch)
// ---------------------------------------------------------------------------
__global__ __launch_bounds__(256) void k_zero() {
    int t = blockIdx.x * 256 + threadIdx.x;
    if (t < NN) g_deg[t] = 0;
    if (blockIdx.x == 0 && threadIdx.x < NBK) g_bhist[threadIdx.x] = 0;
}

__global__ __launch_bounds__(256) void k_hist(const int* __restrict__ ei) {
    int e = blockIdx.x * 256 + threadIdx.x;
    if (e < NE) atomicAdd(&g_deg[ei[e]], 1);   // return unused -> REDG
}

__global__ __launch_bounds__(256) void k_bhist() {
    int n = blockIdx.x * 256 + threadIdx.x;
    if (n < NN) {
        int b = (NBK - 1) - min(g_deg[n], NBK - 1);   // descending degree
        atomicAdd(&g_bhist[b], 1);
    }
}

__global__ __launch_bounds__(256) void k_scan() {
    __shared__ int part[256];
    const int PER = (NN + 255) / 256;   // 40
    int tid = threadIdx.x;
    int base = tid * PER;
    int s = 0;
    for (int k = 0; k < PER; k++) {
        int i = base + k;
        if (i < NN) s += g_deg[i];
    }
    part[tid] = s;
    __syncthreads();
    for (int off = 1; off < 256; off <<= 1) {
        int v = (tid >= off) ? part[tid - off] : 0;
        __syncthreads();
        part[tid] += v;
        __syncthreads();
    }
    int run = tid ? part[tid - 1] : 0;
    for (int k = 0; k < PER; k++) {
        int i = base + k;
        if (i < NN) {
            g_start[i] = run;
            g_cur[i] = run;
            run += g_deg[i];
        }
    }
    if (tid == 255) g_start[NN] = part[255];

    // --- bucket scan for node schedule (tiny, serial on smem copy) ---
    __shared__ int bh[NBK];
    if (tid < NBK) bh[tid] = g_bhist[tid];
    __syncthreads();
    if (tid == 0) {
        int brun = 0;
        for (int b = 0; b < NBK; b++) {
            g_bcur[b] = brun;
            brun += bh[b];
        }
    }
}

__global__ __launch_bounds__(256) void k_scatter(const int* __restrict__ ei,
                                                 const float* __restrict__ ea) {
    int e = blockIdx.x * 256 + threadIdx.x;
    if (e >= NE) return;
    int src = ei[e];
    int pos = atomicAdd(&g_cur[src], 1);
    g_sdst[pos] = ei[NE + e];
    g_sea[pos] = make_float2(ea[2 * e], ea[2 * e + 1]);
}

__global__ __launch_bounds__(256) void k_order() {
    int n = blockIdx.x * 256 + threadIdx.x;
    if (n >= NN) return;
    int b = (NBK - 1) - min(g_deg[n], NBK - 1);
    int pos = atomicAdd(&g_bcur[b], 1);
    g_order[pos] = n;
}

// ---------------------------------------------------------------------------
// kAF: fused G-GEMM + B + agg-init.  16 nodes per 256-thread block.
//   G[n, j*32+o] = sum_i x[n,i] * w2[j*(DIN*32) + i*32 + o]
//   B[n,o]      = sum_i x[n,i] * b2[i*32+o]
//   agg[wr][n,o]= bias[o] + sum_i x[n,i]*root[i*32+o]
// ---------------------------------------------------------------------------
template<int DIN, int MODE>
__global__ __launch_bounds__(256) void kAF(const float* __restrict__ xext,
                                           const float* __restrict__ w2,
                                           const float* __restrict__ b2,
                                           const float* __restrict__ root,
                                           const float* __restrict__ bias,
                                           int rd, int wr) {
    __shared__ float xsf[16][DIN];
    __shared__ ull   xs2[8][DIN];
    const int base = blockIdx.x * 16;
    const int tid = threadIdx.x;

    for (int idx = tid; idx < 16 * DIN; idx += 256) {
        int m = idx / DIN, i = idx % DIN;
        int n = base + m;
        xsf[m][i] = MODE ? fmaxf(g_agg[rd][n * DIN + i], 0.f)
                         : xext[n * DIN + i];
    }
    __syncthreads();
    for (int idx = tid; idx < 8 * DIN; idx += 256) {
        int p = idx / DIN, i = idx % DIN;
        ull t;
        PACK2(t, xsf[2 * p][i], xsf[2 * p + 1][i]);
        xs2[p][i] = t;
    }
    __syncthreads();

    ull acc2[8][4];
#pragma unroll
    for (int p = 0; p < 8; p++)
#pragma unroll
        for (int k = 0; k < 4; k++) PACK2(acc2[p][k], 0.f, 0.f);

#pragma unroll 4
    for (int i = 0; i < DIN; i++) {
        ull wp[4];
#pragma unroll
        for (int k = 0; k < 4; k++) {
            int col = tid + 256 * k;                  // col = j*32 + o
            float wv = w2[(col >> 5) * (DIN * 32) + i * 32 + (col & 31)];
            PACK2(wp[k], wv, wv);
        }
#pragma unroll
        for (int p = 0; p < 8; p++) {
            ull x2 = xs2[p][i];
#pragma unroll
            for (int k = 0; k < 4; k++) FMA2(acc2[p][k], x2, wp[k], acc2[p][k]);
        }
    }

#pragma unroll
    for (int p = 0; p < 8; p++) {
        int n0 = base + 2 * p;
#pragma unroll
        for (int k = 0; k < 4; k++) {
            float v0, v1;
            UNPACK2(v0, v1, acc2[p][k]);
            g_G[(size_t)n0 * 1024 + tid + 256 * k]       = v0;
            g_G[(size_t)(n0 + 1) * 1024 + tid + 256 * k] = v1;
        }
    }

    // --- B + agg-init: 512 (m,o) pairs over 256 threads ---
#pragma unroll
    for (int t = tid; t < 512; t += 256) {
        int m = t >> 5, o = t & 31;
        float b = 0.f;
        float a = bias[o];
#pragma unroll 4
        for (int i = 0; i < DIN; i++) {
            float xv = xsf[m][i];
            b = fmaf(xv, b2[i * 32 + o], b);
            a = fmaf(xv, root[i * 32 + o], a);
        }
        int n = base + m;
        g_B[n * 32 + o] = b;
        g_agg[wr][n * 32 + o] = a;
    }
}

// ---------------------------------------------------------------------------
// kB3: one warp per SOURCE node, nodes taken in descending-degree order
// (g_order) so co-resident warps have near-equal work and big nodes start
// first. 128-thread blocks for finer residency granularity.
//  - warp loads G[n] once into 16 packed f32x2 register pairs per lane
//  - h staged through smem: 1 STS/edge, LDS.128 broadcast reads
//  - 2 edges interleaved: 4 independent FFMA2 chains (latency overlap)
//  - 128B-coalesced REDG scatter to agg[wr][dst]
// ---------------------------------------------------------------------------
__global__ __launch_bounds__(128) void kB3(const float* __restrict__ w1,
                                           const float* __restrict__ b1, int wr) {
    __shared__ __align__(16) float hs[4][EB][32];
    const int w = threadIdx.x >> 5;
    const int lane = threadIdx.x & 31;
    const int n = g_order[blockIdx.x * 4 + w];       // grid*4 == NN exactly
    const int beg = g_start[n], end = g_start[n + 1];
    if (beg == end) return;

    const float w10 = w1[lane], w11 = w1[32 + lane], b1v = b1[lane];
    const float* __restrict__ Gs = g_G + (size_t)n * 1024;

    ull G2[16];
#pragma unroll
    for (int q = 0; q < 16; q++) {
        float g0 = Gs[(2 * q) * 32 + lane];
        float g1 = Gs[(2 * q + 1) * 32 + lane];
        PACK2(G2[q], g0, g1);
    }
    float Bv = g_B[n * 32 + lane];
    ull accInit, zero2;
    PACK2(accInit, Bv, 0.f);
    PACK2(zero2, 0.f, 0.f);
    float* __restrict__ aggp = g_agg[wr];

    for (int e0 = beg; e0 < end; e0 += EB) {
        const int cnt = min(EB, end - e0);
#pragma unroll
        for (int k = 0; k < EB; k++) {
            if (k < cnt) {
                float2 a = g_sea[e0 + k];
                hs[w][k][lane] = fmaxf(fmaf(a.x, w10, fmaf(a.y, w11, b1v)), 0.f);
            }
        }
        __syncwarp();
        int k = 0;
        for (; k + 2 <= cnt; k += 2) {
            int d0 = g_sdst[e0 + k];
            int d1 = g_sdst[e0 + k + 1];
            const ulonglong2* __restrict__ hp0 =
                reinterpret_cast<const ulonglong2*>(hs[w][k]);
            const ulonglong2* __restrict__ hp1 =
                reinterpret_cast<const ulonglong2*>(hs[w][k + 1]);
            ull a0 = accInit, a1 = zero2;
            ull c0 = accInit, c1 = zero2;
#pragma unroll
            for (int q = 0; q < 8; q++) {
                ulonglong2 h0 = hp0[q];
                ulonglong2 h1 = hp1[q];
                FMA2(a0, h0.x, G2[2 * q], a0);
                FMA2(a1, h0.y, G2[2 * q + 1], a1);
                FMA2(c0, h1.x, G2[2 * q], c0);
                FMA2(c1, h1.y, G2[2 * q + 1], c1);
            }
            float l0, h0f, l1, h1f;
            UNPACK2(l0, h0f, a0);
            UNPACK2(l1, h1f, a1);
            atomicAdd(&aggp[d0 * 32 + lane], (l0 + h0f) + (l1 + h1f));
            UNPACK2(l0, h0f, c0);
            UNPACK2(l1, h1f, c1);
            atomicAdd(&aggp[d1 * 32 + lane], (l0 + h0f) + (l1 + h1f));
        }
        if (k < cnt) {
            int d0 = g_sdst[e0 + k];
            const ulonglong2* __restrict__ hp0 =
                reinterpret_cast<const ulonglong2*>(hs[w][k]);
            ull a0 = accInit, a1 = zero2;
#pragma unroll
            for (int q = 0; q < 8; q++) {
                ulonglong2 h0 = hp0[q];
                FMA2(a0, h0.x, G2[2 * q], a0);
                FMA2(a1, h0.y, G2[2 * q + 1], a1);
            }
            float l0, h0f, l1, h1f;
            UNPACK2(l0, h0f, a0);
            UNPACK2(l1, h1f, a1);
            atomicAdd(&aggp[d0 * 32 + lane], (l0 + h0f) + (l1 + h1f));
        }
        __syncwarp();
    }
}

// ---------------------------------------------------------------------------
// kF: relu -> logits = x @ fc_w + fc_b -> log_softmax
// ---------------------------------------------------------------------------
__global__ __launch_bounds__(256) void kF(const float* __restrict__ fcw,
                                          const float* __restrict__ fcb,
                                          float* __restrict__ out, int rd) {
    int n = blockIdx.x * 256 + threadIdx.x;
    if (n >= NN) return;
    float l[NC];
#pragma unroll
    for (int c = 0; c < NC; c++) l[c] = fcb[c];
    const float4* xr = reinterpret_cast<const float4*>(g_agg[rd]) + n * 8;
#pragma unroll
    for (int q = 0; q < 8; q++) {
        float4 v = xr[q];
        float xv[4] = {fmaxf(v.x, 0.f), fmaxf(v.y, 0.f),
                       fmaxf(v.z, 0.f), fmaxf(v.w, 0.f)};
#pragma unroll
        for (int s = 0; s < 4; s++) {
            int o = q * 4 + s;
#pragma unroll
            for (int c = 0; c < NC; c++) l[c] = fmaf(xv[s], fcw[o * NC + c], l[c]);
        }
    }
    float m = l[0];
#pragma unroll
    for (int c = 1; c < NC; c++) m = fmaxf(m, l[c]);
    float s = 0.f;
#pragma unroll
    for (int c = 0; c < NC; c++) s += expf(l[c] - m);
    float lse = m + logf(s);
#pragma unroll
    for (int c = 0; c < NC; c++) out[n * NC + c] = l[c] - lse;
}

// ---------------------------------------------------------------------------
extern "C" void kernel_launch(void* const* d_in, const int* in_sizes, int n_in,
                              void* d_out, int out_size) {
    const float* x   = (const float*)d_in[0];   // [N, 4]
    const int*   ei  = (const int*)d_in[1];     // [2, E]
    const float* ea  = (const float*)d_in[2];   // [E, 2]
    const float *W1[3], *B1[3], *W2[3], *B2[3], *RT[3], *BI[3];
    for (int l = 0; l < 3; l++) {
        W1[l] = (const float*)d_in[3 + 6 * l + 0];
        B1[l] = (const float*)d_in[3 + 6 * l + 1];
        W2[l] = (const float*)d_in[3 + 6 * l + 2];
        B2[l] = (const float*)d_in[3 + 6 * l + 3];
        RT[l] = (const float*)d_in[3 + 6 * l + 4];
        BI[l] = (const float*)d_in[3 + 6 * l + 5];
    }
    const float* fcw = (const float*)d_in[21];
    const float* fcb = (const float*)d_in[22];
    float* out = (float*)d_out;

    const int gA = NN / 16;                     // 625 (exact)
    const int gB = NN / 4;                      // 2500 blocks x 4 warps
    const int gE = (NE + 255) / 256;            // 625
    const int gF = (NN + 255) / 256;
    const int gZ = (NN + 255) / 256;

    // ---- edge sort by src + degree-ordered node schedule (once) ----
    k_zero<<<gZ, 256>>>();
    k_hist<<<gE, 256>>>(ei);
    k_bhist<<<gZ, 256>>>();
    k_scan<<<1, 256>>>();
    k_scatter<<<gE, 256>>>(ei, ea);
    k_order<<<gZ, 256>>>();

    // ---- layer 0 (din=4, external input, write agg[0]) ----
    kAF<FIN, 0><<<gA, 256>>>(x, W2[0], B2[0], RT[0], BI[0], 0, 0);
    kB3<<<gB, 128>>>(W1[0], B1[0], 0);

    // ---- layer 1 (din=32, read agg[0] w/ relu, write agg[1]) ----
    kAF<HID, 1><<<gA, 256>>>(nullptr, W2[1], B2[1], RT[1], BI[1], 0, 1);
    kB3<<<gB, 128>>>(W1[1], B1[1], 1);

    // ---- layer 2 (din=32, read agg[1] w/ relu, write agg[0]) ----
    kAF<HID, 1><<<gA, 256>>>(nullptr, W2[2], B2[2], RT[2], BI[2], 1, 0);
    kB3<<<gB, 128>>>(W1[2], B1[2], 0);

    // ---- classifier + log_softmax (relu on read) ----
    kF<<<gF, 256>>>(fcw, fcb, out, 0);
}

// round 14
// speedup vs baseline: 1.1042x; 1.0730x over previous
#include <cuda_runtime.h>
#include <math.h>

// Problem constants
#define NN 10000      // nodes
#define NE 160000     // edges
#define FIN 4         // input features
#define HID 32        // hidden
#define NC 4          // classes
#define EB 8          // edges per smem batch in kB3

typedef unsigned long long ull;

// ---- packed fp32x2 helpers (sm_103a) ----
#define FMA2(d, a, b, c) \
    asm("fma.rn.f32x2 %0, %1, %2, %3;" : "=l"(d) : "l"(a), "l"(b), "l"(c))
#define PACK2(d, lo, hi) \
    asm("mov.b64 %0, {%1, %2};" : "=l"(d) : "r"(__float_as_uint(lo)), "r"(__float_as_uint(hi)))
#define UNPACK2(lo, hi, v) do { unsigned _ul, _uh;                        \
    asm("mov.b64 {%0, %1}, %2;" : "=r"(_ul), "=r"(_uh) : "l"(v));          \
    lo = __uint_as_float(_ul); hi = __uint_as_float(_uh); } while (0)

// ---------------- device scratch (static globals: allowed) ----------------
__device__ float g_G[NN * HID * HID];    // [n, j, o]  40.96 MB (L2-resident)
__device__ float g_B[NN * HID];          // per-src b2 term
__device__ float g_agg[2][NN * HID];     // ping-pong accumulators
// edge sort-by-src structures
__device__ int    g_deg[NN];
__device__ int    g_start[NN + 1];
__device__ int    g_cur[NN];
__device__ int    g_sdst[NE];
__device__ float2 g_sea[NE];

// ---------------------------------------------------------------------------
// Edge counting sort (once per launch; edges shared by all 3 layers)
// ---------------------------------------------------------------------------
__global__ __launch_bounds__(1024) void k_zero() {
    int t = blockIdx.x * 1024 + threadIdx.x;
    if (t < NN) g_deg[t] = 0;
}

__global__ __launch_bounds__(1024) void k_hist(const int* __restrict__ ei) {
    int e = blockIdx.x * 1024 + threadIdx.x;
    if (e < NE) atomicAdd(&g_deg[ei[e]], 1);   // return unused -> REDG
}

// Single-block exclusive scan, 1024 threads, PER=10 bins/thread.
// Degrees cached in REGISTERS on first pass -> writeback has no serial
// global loads (the 21us bug in the previous version).
__global__ __launch_bounds__(1024) void k_scan() {
    __shared__ int part[1024];
    const int PER = (NN + 1023) / 1024;       // 10
    const int tid = threadIdx.x;
    const int base = tid * PER;

    int d[PER];
    int s = 0;
#pragma unroll
    for (int k = 0; k < PER; k++) {
        int i = base + k;
        d[k] = (i < NN) ? g_deg[i] : 0;       // independent loads, MLP=10
        s += d[k];
    }
    part[tid] = s;
    __syncthreads();
#pragma unroll
    for (int off = 1; off < 1024; off <<= 1) {
        int v = (tid >= off) ? part[tid - off] : 0;
        __syncthreads();
        part[tid] += v;
        __syncthreads();
    }
    int run = tid ? part[tid - 1] : 0;
#pragma unroll
    for (int k = 0; k < PER; k++) {
        int i = base + k;
        if (i < NN) {
            g_start[i] = run;
            g_cur[i] = run;
            run += d[k];                      // register, no global reload
        }
    }
    if (tid == 1023) g_start[NN] = part[1023];
}

__global__ __launch_bounds__(256) void k_scatter(const int* __restrict__ ei,
                                                 const float* __restrict__ ea) {
    int e = blockIdx.x * 256 + threadIdx.x;
    if (e >= NE) return;
    int src = ei[e];
    int pos = atomicAdd(&g_cur[src], 1);
    g_sdst[pos] = ei[NE + e];
    g_sea[pos] = make_float2(ea[2 * e], ea[2 * e + 1]);
}

// ---------------------------------------------------------------------------
// kAF: fused G-GEMM + B + agg-init.  16 nodes per 256-thread block.
//   G[n, j*32+o] = sum_i x[n,i] * w2[j*(DIN*32) + i*32 + o]
//   B[n,o]      = sum_i x[n,i] * b2[i*32+o]
//   agg[wr][n,o]= bias[o] + sum_i x[n,i]*root[i*32+o]
// ---------------------------------------------------------------------------
template<int DIN, int MODE>
__global__ __launch_bounds__(256) void kAF(const float* __restrict__ xext,
                                           const float* __restrict__ w2,
                                           const float* __restrict__ b2,
                                           const float* __restrict__ root,
                                           const float* __restrict__ bias,
                                           int rd, int wr) {
    __shared__ float xsf[16][DIN];
    __shared__ ull   xs2[8][DIN];
    const int base = blockIdx.x * 16;
    const int tid = threadIdx.x;

    for (int idx = tid; idx < 16 * DIN; idx += 256) {
        int m = idx / DIN, i = idx % DIN;
        int n = base + m;
        xsf[m][i] = MODE ? fmaxf(g_agg[rd][n * DIN + i], 0.f)
                         : xext[n * DIN + i];
    }
    __syncthreads();
    for (int idx = tid; idx < 8 * DIN; idx += 256) {
        int p = idx / DIN, i = idx % DIN;
        ull t;
        PACK2(t, xsf[2 * p][i], xsf[2 * p + 1][i]);
        xs2[p][i] = t;
    }
    __syncthreads();

    ull acc2[8][4];
#pragma unroll
    for (int p = 0; p < 8; p++)
#pragma unroll
        for (int k = 0; k < 4; k++) PACK2(acc2[p][k], 0.f, 0.f);

#pragma unroll 4
    for (int i = 0; i < DIN; i++) {
        ull wp[4];
#pragma unroll
        for (int k = 0; k < 4; k++) {
            int col = tid + 256 * k;                  // col = j*32 + o
            float wv = w2[(col >> 5) * (DIN * 32) + i * 32 + (col & 31)];
            PACK2(wp[k], wv, wv);
        }
#pragma unroll
        for (int p = 0; p < 8; p++) {
            ull x2 = xs2[p][i];
#pragma unroll
            for (int k = 0; k < 4; k++) FMA2(acc2[p][k], x2, wp[k], acc2[p][k]);
        }
    }

#pragma unroll
    for (int p = 0; p < 8; p++) {
        int n0 = base + 2 * p;
#pragma unroll
        for (int k = 0; k < 4; k++) {
            float v0, v1;
            UNPACK2(v0, v1, acc2[p][k]);
            g_G[(size_t)n0 * 1024 + tid + 256 * k]       = v0;
            g_G[(size_t)(n0 + 1) * 1024 + tid + 256 * k] = v1;
        }
    }

    // --- B + agg-init: 512 (m,o) pairs over 256 threads ---
#pragma unroll
    for (int t = tid; t < 512; t += 256) {
        int m = t >> 5, o = t & 31;
        float b = 0.f;
        float a = bias[o];
#pragma unroll 4
        for (int i = 0; i < DIN; i++) {
            float xv = xsf[m][i];
            b = fmaf(xv, b2[i * 32 + o], b);
            a = fmaf(xv, root[i * 32 + o], a);
        }
        int n = base + m;
        g_B[n * 32 + o] = b;
        g_agg[wr][n * 32 + o] = a;
    }
}

// ---------------------------------------------------------------------------
// kB3: one warp per SOURCE node (edges pre-sorted by src), 128-thr blocks.
//  - warp loads G[n] once into 16 packed f32x2 register pairs per lane
//  - h staged through smem: 1 STS/edge, LDS.128 broadcast reads
//  - 2 edges interleaved: 4 independent FFMA2 chains (latency overlap)
//  - 128B-coalesced REDG scatter to agg[wr][dst]
// ---------------------------------------------------------------------------
__global__ __launch_bounds__(128) void kB3(const float* __restrict__ w1,
                                           const float* __restrict__ b1, int wr) {
    __shared__ __align__(16) float hs[4][EB][32];
    const int w = threadIdx.x >> 5;
    const int lane = threadIdx.x & 31;
    const int n = blockIdx.x * 4 + w;                // grid*4 == NN exactly
    const int beg = g_start[n], end = g_start[n + 1];
    if (beg == end) return;

    const float w10 = w1[lane], w11 = w1[32 + lane], b1v = b1[lane];
    const float* __restrict__ Gs = g_G + (size_t)n * 1024;

    ull G2[16];
#pragma unroll
    for (int q = 0; q < 16; q++) {
        float g0 = Gs[(2 * q) * 32 + lane];
        float g1 = Gs[(2 * q + 1) * 32 + lane];
        PACK2(G2[q], g0, g1);
    }
    float Bv = g_B[n * 32 + lane];
    ull accInit, zero2;
    PACK2(accInit, Bv, 0.f);
    PACK2(zero2, 0.f, 0.f);
    float* __restrict__ aggp = g_agg[wr];

    for (int e0 = beg; e0 < end; e0 += EB) {
        const int cnt = min(EB, end - e0);
#pragma unroll
        for (int k = 0; k < EB; k++) {
            if (k < cnt) {
                float2 a = g_sea[e0 + k];
                hs[w][k][lane] = fmaxf(fmaf(a.x, w10, fmaf(a.y, w11, b1v)), 0.f);
            }
        }
        __syncwarp();
        int k = 0;
        for (; k + 2 <= cnt; k += 2) {
            int d0 = g_sdst[e0 + k];
            int d1 = g_sdst[e0 + k + 1];
            const ulonglong2* __restrict__ hp0 =
                reinterpret_cast<const ulonglong2*>(hs[w][k]);
            const ulonglong2* __restrict__ hp1 =
                reinterpret_cast<const ulonglong2*>(hs[w][k + 1]);
            ull a0 = accInit, a1 = zero2;
            ull c0 = accInit, c1 = zero2;
#pragma unroll
            for (int q = 0; q < 8; q++) {
                ulonglong2 h0 = hp0[q];
                ulonglong2 h1 = hp1[q];
                FMA2(a0, h0.x, G2[2 * q], a0);
                FMA2(a1, h0.y, G2[2 * q + 1], a1);
                FMA2(c0, h1.x, G2[2 * q], c0);
                FMA2(c1, h1.y, G2[2 * q + 1], c1);
            }
            float l0, h0f, l1, h1f;
            UNPACK2(l0, h0f, a0);
            UNPACK2(l1, h1f, a1);
            atomicAdd(&aggp[d0 * 32 + lane], (l0 + h0f) + (l1 + h1f));
            UNPACK2(l0, h0f, c0);
            UNPACK2(l1, h1f, c1);
            atomicAdd(&aggp[d1 * 32 + lane], (l0 + h0f) + (l1 + h1f));
        }
        if (k < cnt) {
            int d0 = g_sdst[e0 + k];
            const ulonglong2* __restrict__ hp0 =
                reinterpret_cast<const ulonglong2*>(hs[w][k]);
            ull a0 = accInit, a1 = zero2;
#pragma unroll
            for (int q = 0; q < 8; q++) {
                ulonglong2 h0 = hp0[q];
                FMA2(a0, h0.x, G2[2 * q], a0);
                FMA2(a1, h0.y, G2[2 * q + 1], a1);
            }
            float l0, h0f, l1, h1f;
            UNPACK2(l0, h0f, a0);
            UNPACK2(l1, h1f, a1);
            atomicAdd(&aggp[d0 * 32 + lane], (l0 + h0f) + (l1 + h1f));
        }
        __syncwarp();
    }
}

// ---------------------------------------------------------------------------
// kF: relu -> logits = x @ fc_w + fc_b -> log_softmax
// ---------------------------------------------------------------------------
__global__ __launch_bounds__(256) void kF(const float* __restrict__ fcw,
                                          const float* __restrict__ fcb,
                                          float* __restrict__ out, int rd) {
    int n = blockIdx.x * 256 + threadIdx.x;
    if (n >= NN) return;
    float l[NC];
#pragma unroll
    for (int c = 0; c < NC; c++) l[c] = fcb[c];
    const float4* xr = reinterpret_cast<const float4*>(g_agg[rd]) + n * 8;
#pragma unroll
    for (int q = 0; q < 8; q++) {
        float4 v = xr[q];
        float xv[4] = {fmaxf(v.x, 0.f), fmaxf(v.y, 0.f),
                       fmaxf(v.z, 0.f), fmaxf(v.w, 0.f)};
#pragma unroll
        for (int s = 0; s < 4; s++) {
            int o = q * 4 + s;
#pragma unroll
            for (int c = 0; c < NC; c++) l[c] = fmaf(xv[s], fcw[o * NC + c], l[c]);
        }
    }
    float m = l[0];
#pragma unroll
    for (int c = 1; c < NC; c++) m = fmaxf(m, l[c]);
    float s = 0.f;
#pragma unroll
    for (int c = 0; c < NC; c++) s += expf(l[c] - m);
    float lse = m + logf(s);
#pragma unroll
    for (int c = 0; c < NC; c++) out[n * NC + c] = l[c] - lse;
}

// ---------------------------------------------------------------------------
extern "C" void kernel_launch(void* const* d_in, const int* in_sizes, int n_in,
                              void* d_out, int out_size) {
    const float* x   = (const float*)d_in[0];   // [N, 4]
    const int*   ei  = (const int*)d_in[1];     // [2, E]
    const float* ea  = (const float*)d_in[2];   // [E, 2]
    const float *W1[3], *B1[3], *W2[3], *B2[3], *RT[3], *BI[3];
    for (int l = 0; l < 3; l++) {
        W1[l] = (const float*)d_in[3 + 6 * l + 0];
        B1[l] = (const float*)d_in[3 + 6 * l + 1];
        W2[l] = (const float*)d_in[3 + 6 * l + 2];
        B2[l] = (const float*)d_in[3 + 6 * l + 3];
        RT[l] = (const float*)d_in[3 + 6 * l + 4];
        BI[l] = (const float*)d_in[3 + 6 * l + 5];
    }
    const float* fcw = (const float*)d_in[21];
    const float* fcb = (const float*)d_in[22];
    float* out = (float*)d_out;

    const int gA = NN / 16;                     // 625 (exact)
    const int gB = NN / 4;                      // 2500 blocks x 4 warps
    const int gE = (NE + 255) / 256;            // 625
    const int gF = (NN + 255) / 256;

    // ---- sort edges by src (once; shared by all layers) ----
    k_zero<<<(NN + 1023) / 1024, 1024>>>();
    k_hist<<<(NE + 1023) / 1024, 1024>>>(ei);
    k_scan<<<1, 1024>>>();
    k_scatter<<<gE, 256>>>(ei, ea);

    // ---- layer 0 (din=4, external input, write agg[0]) ----
    kAF<FIN, 0><<<gA, 256>>>(x, W2[0], B2[0], RT[0], BI[0], 0, 0);
    kB3<<<gB, 128>>>(W1[0], B1[0], 0);

    // ---- layer 1 (din=32, read agg[0] w/ relu, write agg[1]) ----
    kAF<HID, 1><<<gA, 256>>>(nullptr, W2[1], B2[1], RT[1], BI[1], 0, 1);
    kB3<<<gB, 128>>>(W1[1], B1[1], 1);

    // ---- layer 2 (din=32, read agg[1] w/ relu, write agg[0]) ----
    kAF<HID, 1><<<gA, 256>>>(nullptr, W2[2], B2[2], RT[2], BI[2], 1, 0);
    kB3<<<gB, 128>>>(W1[2], B1[2], 0);

    // ---- classifier + log_softmax (relu on read) ----
    kF<<<gF, 256>>>(fcw, fcb, out, 0);
}